// round 16
// baseline (speedup 1.0000x reference)
#include <cuda_runtime.h>
#include <cuda_fp16.h>

#define N0V   8192
#define N1V   100000
#define N2V   300000
#define KNBR  32
#define DD    64

typedef unsigned long long u64t;

#define PACKU64(out, lo, hi)  asm("mov.b64 %0, {%1, %2};" : "=l"(out) : "f"(lo), "f"(hi))
#define SPLATF64(out, v)      asm("mov.b64 %0, {%1, %1};" : "=l"(out) : "f"(v))
#define UNPACKF64(lo, hi, in) asm("mov.b64 {%0, %1}, %2;" : "=f"(lo), "=f"(hi) : "l"(in))
#define FFMA2(acc, a, b)      asm("fma.rn.f32x2 %0, %1, %2, %0;" : "+l"(acc) : "l"(a), "l"(b))

// Scratch (device globals — allocation in kernel_launch is forbidden).
__device__ __half g_v2h[(size_t)N2V * DD];    // 38.4 MB gather target
__device__ __half g_agg1[(size_t)N1V * DD];   // 12.8 MB hop-1 aggregates
__device__ __half g_h1h[(size_t)N1V * DD];    // 12.8 MB hop-1 activations
__device__ __half g_agg0[(size_t)N0V * DD];   // 1 MB   seed aggregates

// ---------------------------------------------------------------------------
// K1: v2h = half(feats[node_ids2]); 4 rows per thread.
// ---------------------------------------------------------------------------
__global__ void gather_v2h_kernel(const float* __restrict__ feats,
                                  const int*   __restrict__ node_ids2)
{
    int t = blockIdx.x * blockDim.x + threadIdx.x;
    const int Q = N2V / 4;
    const int quarter_total = Q * (DD / 4);
    if (t >= quarter_total) return;
    int row = t >> 4;
    int c   = t & 15;

    int src[4];
    #pragma unroll
    for (int q = 0; q < 4; ++q)
        src[q] = __ldg(node_ids2 + row + q * Q);

    float4 v[4];
    #pragma unroll
    for (int q = 0; q < 4; ++q)
        v[q] = __ldg((const float4*)(feats + (size_t)src[q] * DD) + c);

    #pragma unroll
    for (int q = 0; q < 4; ++q) {
        __half2 h0 = __floats2half2_rn(v[q].x, v[q].y);
        __half2 h1 = __floats2half2_rn(v[q].z, v[q].w);
        uint2 p;
        p.x = *(unsigned int*)&h0;
        p.y = *(unsigned int*)&h1;
        ((uint2*)g_v2h)[(size_t)(row + q * Q) * 16 + c] = p;
    }
}

// ---------------------------------------------------------------------------
// Gather-mean, 1 row/warp. Index prelude before the PDL grid-dependency sync.
// ---------------------------------------------------------------------------
__global__ void __launch_bounds__(256) agg_mean1_kernel(
    const uint4* __restrict__ vsrc,
    const int*   __restrict__ nbr,
    __half*      __restrict__ aggout,
    int nrows)
{
    const int tid  = threadIdx.x;
    const int lane = tid & 31;
    const int warp = tid >> 5;
    const int row  = blockIdx.x * 8 + warp;
    const int cr   = min(row, nrows - 1);

    // Prelude: neighbor indices are independent of the predecessor kernel.
    const int idx = __ldg(nbr + (size_t)cr * KNBR + lane);

    cudaGridDependencySynchronize();

    if (row >= nrows) return;
    const int sub = lane >> 3;
    const int ch  = lane & 7;

    __half2 zero = __float2half2_rn(0.f);
    __half2 acc[2][4];
    #pragma unroll
    for (int s = 0; s < 2; ++s)
        #pragma unroll
        for (int j = 0; j < 4; ++j) acc[s][j] = zero;

    #pragma unroll
    for (int i = 0; i < 8; ++i) {
        int n = __shfl_sync(0xffffffffu, idx, 4 * i + sub);
        uint4 d = __ldg(vsrc + (size_t)n * 8 + ch);
        const __half2* h = (const __half2*)&d;
        int s = i & 1;
        #pragma unroll
        for (int j = 0; j < 4; ++j)
            acc[s][j] = __hadd2(acc[s][j], h[j]);
    }

    float f[8];
    #pragma unroll
    for (int j = 0; j < 4; ++j) {
        float2 v = __half22float2(__hadd2(acc[0][j], acc[1][j]));
        f[2 * j] = v.x;  f[2 * j + 1] = v.y;
    }
    #pragma unroll
    for (int d = 8; d <= 16; d <<= 1)
        #pragma unroll
        for (int j = 0; j < 8; ++j)
            f[j] += __shfl_xor_sync(0xffffffffu, f[j], d);

    const float inv = 1.0f / KNBR;
    if (sub == 0) {
        __half2 h[4];
        #pragma unroll
        for (int j = 0; j < 4; ++j)
            h[j] = __floats2half2_rn(f[2 * j] * inv, f[2 * j + 1] * inv);
        ((uint4*)aggout)[(size_t)row * 8 + ch] = *(uint4*)h;
    }
}

// ---------------------------------------------------------------------------
// FFMA GEMM: out = relu(A @ W + b), A fp16 [nrows,64].
// W + bias prelude before the PDL grid-dependency sync.
// ---------------------------------------------------------------------------
#define SA_STRIDE 68

template<bool HALF_OUT>
__global__ void __launch_bounds__(256) gemm64_kernel(
    const __half* __restrict__ A,
    const float*  __restrict__ W,
    const float*  __restrict__ bias,
    void*         __restrict__ out,
    int nrows)
{
    __shared__ float  sW[DD * DD];
    __shared__ __half sA[128 * SA_STRIDE];

    const int tid = threadIdx.x;

    #pragma unroll
    for (int i = tid; i < DD * DD / 4; i += 256)
        ((float4*)sW)[i] = __ldg((const float4*)W + i);

    const int rp   = tid >> 3;
    const int col0 = (tid & 7) * 8;
    float4 bv0 = __ldg((const float4*)(bias + col0));
    float4 bv1 = __ldg((const float4*)(bias + col0 + 4));

    cudaGridDependencySynchronize();

    const int rowbase = blockIdx.x * 128;
    for (int i = tid; i < 2048; i += 256) {
        int r = i >> 4, c = i & 15;
        int gr = min(rowbase + r, nrows - 1);
        uint2 v = __ldg((const uint2*)(A + (size_t)gr * DD) + c);
        *(uint2*)&sA[r * SA_STRIDE + c * 4] = v;
    }
    __syncthreads();

    u64t bp[4];
    PACKU64(bp[0], bv0.x, bv0.y);  PACKU64(bp[1], bv0.z, bv0.w);
    PACKU64(bp[2], bv1.x, bv1.y);  PACKU64(bp[3], bv1.z, bv1.w);
    u64t acc[4][4];
    #pragma unroll
    for (int r = 0; r < 4; ++r)
        #pragma unroll
        for (int j = 0; j < 4; ++j) acc[r][j] = bp[j];

    #pragma unroll
    for (int k = 0; k < DD; k += 2) {
        ulonglong2 wA01 = *(const ulonglong2*)&sW[k * DD + col0];
        ulonglong2 wA23 = *(const ulonglong2*)&sW[k * DD + col0 + 4];
        ulonglong2 wB01 = *(const ulonglong2*)&sW[(k + 1) * DD + col0];
        ulonglong2 wB23 = *(const ulonglong2*)&sW[(k + 1) * DD + col0 + 4];
        #pragma unroll
        for (int r = 0; r < 4; ++r) {
            __half2 ah = *(const __half2*)&sA[(4 * rp + r) * SA_STRIDE + k];
            float2 af = __half22float2(ah);
            u64t s0, s1;
            SPLATF64(s0, af.x);
            SPLATF64(s1, af.y);
            FFMA2(acc[r][0], s0, wA01.x);  FFMA2(acc[r][1], s0, wA01.y);
            FFMA2(acc[r][2], s0, wA23.x);  FFMA2(acc[r][3], s0, wA23.y);
            FFMA2(acc[r][0], s1, wB01.x);  FFMA2(acc[r][1], s1, wB01.y);
            FFMA2(acc[r][2], s1, wB23.x);  FFMA2(acc[r][3], s1, wB23.y);
        }
    }

    #pragma unroll
    for (int r = 0; r < 4; ++r) {
        int grow = rowbase + 4 * rp + r;
        if (grow >= nrows) continue;
        if (HALF_OUT) {
            __half2 h[4];
            #pragma unroll
            for (int j = 0; j < 4; ++j) {
                float lo, hi;
                UNPACKF64(lo, hi, acc[r][j]);
                h[j] = __floats2half2_rn(fmaxf(lo, 0.f), fmaxf(hi, 0.f));
            }
            *(uint4*)((__half*)out + (size_t)grow * DD + col0) = *(uint4*)h;
        } else {
            float* op = (float*)out + (size_t)grow * DD + col0;
            #pragma unroll
            for (int j = 0; j < 4; ++j) {
                float lo, hi;
                UNPACKF64(lo, hi, acc[r][j]);
                op[2 * j]     = fmaxf(lo, 0.f);
                op[2 * j + 1] = fmaxf(hi, 0.f);
            }
        }
    }
}

// ---------------------------------------------------------------------------
// PDL launch helper (stream 0).
// ---------------------------------------------------------------------------
template<typename... Args>
static void launch_pdl(void (*kern)(Args...), dim3 grid, dim3 block, Args... args)
{
    cudaLaunchConfig_t cfg = {};
    cfg.gridDim  = grid;
    cfg.blockDim = block;
    cfg.stream   = 0;
    cudaLaunchAttribute attr[1];
    attr[0].id = cudaLaunchAttributeProgrammaticStreamSerialization;
    attr[0].val.programmaticStreamSerializationAllowed = 1;
    cfg.attrs = attr;
    cfg.numAttrs = 1;
    cudaLaunchKernelEx(&cfg, kern, args...);
}

// ---------------------------------------------------------------------------
// Inputs: 0 feats, 1 W0, 2 b0, 3 W1, 4 b1, 5 neigh_idx0, 6 neigh_idx1,
//         7 node_ids1 (unused), 8 node_ids2
// Single stream; the full chain K1->K2->K3->K4->K5 is PDL-linked.
// ---------------------------------------------------------------------------
extern "C" void kernel_launch(void* const* d_in, const int* in_sizes, int n_in,
                              void* d_out, int out_size)
{
    const float* feats      = (const float*)d_in[0];
    const float* W0         = (const float*)d_in[1];
    const float* b0         = (const float*)d_in[2];
    const float* W1         = (const float*)d_in[3];
    const float* b1         = (const float*)d_in[4];
    const int*   neigh_idx0 = (const int*)  d_in[5];
    const int*   neigh_idx1 = (const int*)  d_in[6];
    const int*   node_ids2  = (const int*)  d_in[8];
    float*       out        = (float*)d_out;

    __half* v2h;  cudaGetSymbolAddress((void**)&v2h,  g_v2h);
    __half* agg1; cudaGetSymbolAddress((void**)&agg1, g_agg1);
    __half* h1h;  cudaGetSymbolAddress((void**)&h1h,  g_h1h);
    __half* agg0; cudaGetSymbolAddress((void**)&agg0, g_agg0);

    // K1 (no predecessor): plain launch.
    {
        const int quarter_total = (N2V / 4) * (DD / 4);
        gather_v2h_kernel<<<(quarter_total + 255) / 256, 256>>>(feats, node_ids2);
    }
    // K2: hop-1 aggregation, PDL on K1.
    launch_pdl(agg_mean1_kernel, dim3((N1V + 7) / 8), dim3(256),
               (const uint4*)v2h, neigh_idx1, agg1, (int)N1V);
    // K3: hop-1 GEMM, PDL on K2.
    launch_pdl(gemm64_kernel<true>, dim3((N1V + 127) / 128), dim3(256),
               (const __half*)agg1, W0, b0, (void*)h1h, (int)N1V);
    // K4: seed aggregation, PDL on K3.
    launch_pdl(agg_mean1_kernel, dim3(N0V / 8), dim3(256),
               (const uint4*)h1h, neigh_idx0, agg0, (int)N0V);
    // K5: seed GEMM (fp32 out), PDL on K4.
    launch_pdl(gemm64_kernel<false>, dim3(N0V / 128), dim3(256),
               (const __half*)agg0, W1, b1, (void*)out, (int)N0V);
}

// round 17
// speedup vs baseline: 1.5072x; 1.5072x over previous
#include <cuda_runtime.h>
#include <cuda_fp16.h>
#include <mma.h>

using namespace nvcuda;

#define N0V   8192
#define N1V   100000
#define N2V   300000
#define KNBR  32
#define DD    64

typedef unsigned long long u64t;

#define PACKU64(out, lo, hi)  asm("mov.b64 %0, {%1, %2};" : "=l"(out) : "f"(lo), "f"(hi))
#define SPLATF64(out, v)      asm("mov.b64 %0, {%1, %1};" : "=l"(out) : "f"(v))
#define UNPACKF64(lo, hi, in) asm("mov.b64 {%0, %1}, %2;" : "=f"(lo), "=f"(hi) : "l"(in))
#define FFMA2(acc, a, b)      asm("fma.rn.f32x2 %0, %1, %2, %0;" : "+l"(acc) : "l"(a), "l"(b))

// Scratch (device globals — allocation in kernel_launch is forbidden).
// g_h1f padded to a multiple of 128 rows (wmma stores full 16x16 tiles).
#define N1PAD  100096
__device__ __half g_v2h[(size_t)N2V * DD];     // 38.4 MB gather target
__device__ __half g_agg1[(size_t)N1V * DD];    // 12.8 MB hop-1 aggregates
__device__ float  g_h1f[(size_t)N1PAD * DD];   // 25.6 MB hop-1 activations (fp32)
__device__ __half g_agg0[(size_t)N0V * DD];    // 1 MB   seed aggregates

// ---------------------------------------------------------------------------
// K1: v2h = half(feats[node_ids2]); 4 rows per thread.
// ---------------------------------------------------------------------------
__global__ void gather_v2h_kernel(const float* __restrict__ feats,
                                  const int*   __restrict__ node_ids2)
{
    int t = blockIdx.x * blockDim.x + threadIdx.x;
    const int Q = N2V / 4;
    const int quarter_total = Q * (DD / 4);
    if (t >= quarter_total) return;
    int row = t >> 4;
    int c   = t & 15;

    int src[4];
    #pragma unroll
    for (int q = 0; q < 4; ++q)
        src[q] = __ldg(node_ids2 + row + q * Q);

    float4 v[4];
    #pragma unroll
    for (int q = 0; q < 4; ++q)
        v[q] = __ldg((const float4*)(feats + (size_t)src[q] * DD) + c);

    #pragma unroll
    for (int q = 0; q < 4; ++q) {
        __half2 h0 = __floats2half2_rn(v[q].x, v[q].y);
        __half2 h1 = __floats2half2_rn(v[q].z, v[q].w);
        uint2 p;
        p.x = *(unsigned int*)&h0;
        p.y = *(unsigned int*)&h1;
        ((uint2*)g_v2h)[(size_t)(row + q * Q) * 16 + c] = p;
    }
}

// ---------------------------------------------------------------------------
// K2: gather-mean over fp16 rows, 1 row/warp (validated structure).
// ---------------------------------------------------------------------------
__global__ void __launch_bounds__(256) agg_mean1_kernel(
    const uint4* __restrict__ vsrc,    // fp16 rows, 128B = 8 chunks
    const int*   __restrict__ nbr,
    __half*      __restrict__ aggout,
    int nrows)
{
    const int tid  = threadIdx.x;
    const int lane = tid & 31;
    const int warp = tid >> 5;
    const int row  = blockIdx.x * 8 + warp;
    if (row >= nrows) return;

    const int idx = __ldg(nbr + (size_t)row * KNBR + lane);
    const int sub = lane >> 3;
    const int ch  = lane & 7;

    __half2 zero = __float2half2_rn(0.f);
    __half2 acc[2][4];
    #pragma unroll
    for (int s = 0; s < 2; ++s)
        #pragma unroll
        for (int j = 0; j < 4; ++j) acc[s][j] = zero;

    #pragma unroll
    for (int i = 0; i < 8; ++i) {
        int n = __shfl_sync(0xffffffffu, idx, 4 * i + sub);
        uint4 d = __ldg(vsrc + (size_t)n * 8 + ch);
        const __half2* h = (const __half2*)&d;
        int s = i & 1;
        #pragma unroll
        for (int j = 0; j < 4; ++j)
            acc[s][j] = __hadd2(acc[s][j], h[j]);
    }

    float f[8];
    #pragma unroll
    for (int j = 0; j < 4; ++j) {
        float2 v = __half22float2(__hadd2(acc[0][j], acc[1][j]));
        f[2 * j] = v.x;  f[2 * j + 1] = v.y;
    }
    #pragma unroll
    for (int d = 8; d <= 16; d <<= 1)
        #pragma unroll
        for (int j = 0; j < 8; ++j)
            f[j] += __shfl_xor_sync(0xffffffffu, f[j], d);

    const float inv = 1.0f / KNBR;
    if (sub == 0) {
        __half2 h[4];
        #pragma unroll
        for (int j = 0; j < 4; ++j)
            h[j] = __floats2half2_rn(f[2 * j] * inv, f[2 * j + 1] * inv);
        ((uint4*)aggout)[(size_t)row * 8 + ch] = *(uint4*)h;
    }
}

// ---------------------------------------------------------------------------
// K3: lean wmma GEMM  h1f = relu(agg1 @ W0 + b0), fp32 OUT direct to global.
// 8 warps x 16 rows = 128 rows/block. Static smem 30KB (sA + fp16 sW + bias).
// W converted fp32->fp16 in-kernel. Output buffer padded to 128 rows.
// ---------------------------------------------------------------------------
__global__ void __launch_bounds__(256) gemm_wmma_f_kernel(
    const __half* __restrict__ A,
    const float*  __restrict__ W,
    const float*  __restrict__ bias,
    float*        __restrict__ out,    // padded to >= ceil(nrows/128)*128 rows
    int nrows)
{
    __shared__ __half sA[128 * 72];    // 18432 B
    __shared__ __half sW[DD * DD];     // 8192 B
    __shared__ float  sBias[16 * DD];  // 4096 B

    const int tid  = threadIdx.x;
    const int warp = tid >> 5;
    const int rowbase = blockIdx.x * 128;

    // Stage + convert W (fp32 -> fp16).
    #pragma unroll
    for (int i = tid; i < DD * DD; i += 256)
        sW[i] = __float2half(__ldg(W + i));
    // Bias-replicated tile (16 rows x 64).
    for (int i = tid; i < 16 * DD; i += 256)
        sBias[i] = __ldg(bias + (i & (DD - 1)));
    // Stage A rows (clamped).
    for (int i = tid; i < 1024; i += 256) {
        int r = i >> 3, c = i & 7;
        int gr = min(rowbase + r, nrows - 1);
        uint4 v = __ldg((const uint4*)(A + (size_t)gr * DD) + c);
        *(uint4*)(sA + r * 72 + c * 8) = v;
    }
    __syncthreads();

    wmma::fragment<wmma::accumulator, 16, 16, 16, float> acc[4];
    #pragma unroll
    for (int n = 0; n < 4; ++n)
        wmma::load_matrix_sync(acc[n], sBias + n * 16, DD, wmma::mem_row_major);

    #pragma unroll
    for (int k = 0; k < 4; ++k) {
        wmma::fragment<wmma::matrix_a, 16, 16, 16, __half, wmma::row_major> a;
        wmma::load_matrix_sync(a, sA + (warp * 16) * 72 + k * 16, 72);
        #pragma unroll
        for (int n = 0; n < 4; ++n) {
            wmma::fragment<wmma::matrix_b, 16, 16, 16, __half, wmma::row_major> b;
            wmma::load_matrix_sync(b, sW + (k * 16) * DD + n * 16, DD);
            wmma::mma_sync(acc[n], a, b, acc[n]);
        }
    }

    #pragma unroll
    for (int n = 0; n < 4; ++n)
        #pragma unroll
        for (int e = 0; e < acc[n].num_elements; ++e)
            acc[n].x[e] = fmaxf(acc[n].x[e], 0.f);

    const int grow0 = rowbase + warp * 16;   // padded buffer: always in-bounds
    #pragma unroll
    for (int n = 0; n < 4; ++n)
        wmma::store_matrix_sync(out + (size_t)grow0 * DD + n * 16,
                                acc[n], DD, wmma::mem_row_major);
}

// ---------------------------------------------------------------------------
// K4: gather-mean over fp32 rows (h1f), 1 row/warp, fp16 out.
// Row = 256B = 16 chunks; lane = (sub = lane>>4, ch = lane&15); one LDG.128
// covers 2 neighbor rows per instruction. Butterfly over xor 16.
// ---------------------------------------------------------------------------
__global__ void __launch_bounds__(256) agg_mean1f_kernel(
    const uint4* __restrict__ vsrc,    // fp32 rows, 256B = 16 chunks
    const int*   __restrict__ nbr,
    __half*      __restrict__ aggout,
    int nrows)
{
    const int tid  = threadIdx.x;
    const int lane = tid & 31;
    const int warp = tid >> 5;
    const int row  = blockIdx.x * 8 + warp;
    if (row >= nrows) return;

    const int idx = __ldg(nbr + (size_t)row * KNBR + lane);
    const int sub = lane >> 4;      // 2 subgroups
    const int ch  = lane & 15;      // 16B chunk within 256B row

    float f[4] = {0.f, 0.f, 0.f, 0.f};
    #pragma unroll
    for (int i = 0; i < 16; ++i) {
        int n = __shfl_sync(0xffffffffu, idx, 2 * i + sub);
        uint4 d = __ldg(vsrc + (size_t)n * 16 + ch);
        const float* v = (const float*)&d;
        f[0] += v[0];  f[1] += v[1];  f[2] += v[2];  f[3] += v[3];
    }
    #pragma unroll
    for (int j = 0; j < 4; ++j)
        f[j] += __shfl_xor_sync(0xffffffffu, f[j], 16);

    const float inv = 1.0f / KNBR;
    if (sub == 0) {
        __half2 h[2];
        h[0] = __floats2half2_rn(f[0] * inv, f[1] * inv);
        h[1] = __floats2half2_rn(f[2] * inv, f[3] * inv);
        ((uint2*)aggout)[(size_t)row * 16 + ch] = *(uint2*)h;
    }
}

// ---------------------------------------------------------------------------
// K5: FFMA GEMM (validated), fp16 in, fp32 out — seed layer only (64 blocks).
// ---------------------------------------------------------------------------
#define SA_STRIDE 68

__global__ void __launch_bounds__(256) gemm64f_kernel(
    const __half* __restrict__ A,
    const float*  __restrict__ W,
    const float*  __restrict__ bias,
    float*        __restrict__ out,
    int nrows)
{
    __shared__ float  sW[DD * DD];
    __shared__ __half sA[128 * SA_STRIDE];

    const int tid = threadIdx.x;
    #pragma unroll
    for (int i = tid; i < DD * DD / 4; i += 256)
        ((float4*)sW)[i] = __ldg((const float4*)W + i);

    const int rowbase = blockIdx.x * 128;
    for (int i = tid; i < 2048; i += 256) {
        int r = i >> 4, c = i & 15;
        int gr = min(rowbase + r, nrows - 1);
        uint2 v = __ldg((const uint2*)(A + (size_t)gr * DD) + c);
        *(uint2*)&sA[r * SA_STRIDE + c * 4] = v;
    }
    __syncthreads();

    const int rp   = tid >> 3;
    const int col0 = (tid & 7) * 8;

    float4 bv0 = __ldg((const float4*)(bias + col0));
    float4 bv1 = __ldg((const float4*)(bias + col0 + 4));
    u64t bp[4];
    PACKU64(bp[0], bv0.x, bv0.y);  PACKU64(bp[1], bv0.z, bv0.w);
    PACKU64(bp[2], bv1.x, bv1.y);  PACKU64(bp[3], bv1.z, bv1.w);
    u64t acc[4][4];
    #pragma unroll
    for (int r = 0; r < 4; ++r)
        #pragma unroll
        for (int j = 0; j < 4; ++j) acc[r][j] = bp[j];

    #pragma unroll
    for (int k = 0; k < DD; k += 2) {
        ulonglong2 wA01 = *(const ulonglong2*)&sW[k * DD + col0];
        ulonglong2 wA23 = *(const ulonglong2*)&sW[k * DD + col0 + 4];
        ulonglong2 wB01 = *(const ulonglong2*)&sW[(k + 1) * DD + col0];
        ulonglong2 wB23 = *(const ulonglong2*)&sW[(k + 1) * DD + col0 + 4];
        #pragma unroll
        for (int r = 0; r < 4; ++r) {
            __half2 ah = *(const __half2*)&sA[(4 * rp + r) * SA_STRIDE + k];
            float2 af = __half22float2(ah);
            u64t s0, s1;
            SPLATF64(s0, af.x);
            SPLATF64(s1, af.y);
            FFMA2(acc[r][0], s0, wA01.x);  FFMA2(acc[r][1], s0, wA01.y);
            FFMA2(acc[r][2], s0, wA23.x);  FFMA2(acc[r][3], s0, wA23.y);
            FFMA2(acc[r][0], s1, wB01.x);  FFMA2(acc[r][1], s1, wB01.y);
            FFMA2(acc[r][2], s1, wB23.x);  FFMA2(acc[r][3], s1, wB23.y);
        }
    }

    #pragma unroll
    for (int r = 0; r < 4; ++r) {
        int grow = rowbase + 4 * rp + r;
        if (grow >= nrows) continue;
        float* op = out + (size_t)grow * DD + col0;
        #pragma unroll
        for (int j = 0; j < 4; ++j) {
            float lo, hi;
            UNPACKF64(lo, hi, acc[r][j]);
            op[2 * j]     = fmaxf(lo, 0.f);
            op[2 * j + 1] = fmaxf(hi, 0.f);
        }
    }
}

// ---------------------------------------------------------------------------
// Inputs: 0 feats, 1 W0, 2 b0, 3 W1, 4 b1, 5 neigh_idx0, 6 neigh_idx1,
//         7 node_ids1 (unused), 8 node_ids2
// Plain serialized launches only (PDL/stream overlap proven harmful).
// ---------------------------------------------------------------------------
extern "C" void kernel_launch(void* const* d_in, const int* in_sizes, int n_in,
                              void* d_out, int out_size)
{
    const float* feats      = (const float*)d_in[0];
    const float* W0         = (const float*)d_in[1];
    const float* b0         = (const float*)d_in[2];
    const float* W1         = (const float*)d_in[3];
    const float* b1         = (const float*)d_in[4];
    const int*   neigh_idx0 = (const int*)  d_in[5];
    const int*   neigh_idx1 = (const int*)  d_in[6];
    const int*   node_ids2  = (const int*)  d_in[8];
    float*       out        = (float*)d_out;

    __half* v2h;  cudaGetSymbolAddress((void**)&v2h,  g_v2h);
    __half* agg1; cudaGetSymbolAddress((void**)&agg1, g_agg1);
    float*  h1f;  cudaGetSymbolAddress((void**)&h1f,  g_h1f);
    __half* agg0; cudaGetSymbolAddress((void**)&agg0, g_agg0);

    // K1: feature gather + fp16 compress.
    {
        const int quarter_total = (N2V / 4) * (DD / 4);
        gather_v2h_kernel<<<(quarter_total + 255) / 256, 256>>>(feats, node_ids2);
    }
    // K2: hop-1 aggregation (fp16 source).
    agg_mean1_kernel<<<(N1V + 7) / 8, 256>>>(
        (const uint4*)v2h, neigh_idx1, agg1, N1V);
    // K3: hop-1 GEMM on tensor cores, fp32 out.
    gemm_wmma_f_kernel<<<(N1V + 127) / 128, 256>>>(
        agg1, W0, b0, h1f, N1V);
    // K4: seed aggregation (fp32 source, fp16 out).
    agg_mean1f_kernel<<<N0V / 8, 256>>>(
        (const uint4*)h1f, neigh_idx0, agg0, N0V);
    // K5: seed GEMM (fp16 in, fp32 out).
    gemm64f_kernel<<<N0V / 128, 256>>>(
        agg0, W1, b1, out, N0V);
}